// round 16
// baseline (speedup 1.0000x reference)
#include <cuda_runtime.h>
#include <cuda_bf16.h>
#include <math.h>
#include <stdint.h>

#define BB 2
#define CC 512
#define SS 8192
#define NHW 1024
#define SQRT_C     22.627416997969522f
#define INV_SQRT_C 0.04419417382415922f

#define KSLAB 64
#define MKP 72
#define SZ_MK  (128 * MKP * 2)   // 18432 B  (128-row tile)
#define SZ_MKB (256 * MKP * 2)   // 36864 B  (256-row tile)
#define HALF_MK 64
#define SMEM_GEMM (3 * 2 * SZ_MK)          // 110592 B (128-thread kernels)
#define SMEM_WIDE (3 * (SZ_MK + SZ_MKB))   // 165888 B (256-thread kernels)
#define SMEM_NT   (512 * 33 * 4)           // 67584 B

// Scratch
__device__ float         g_scale[(size_t)BB * SS];
__device__ __nv_bfloat16 g_hn[(size_t)BB * SS * CC];   // [b][s][c]
__device__ __nv_bfloat16 g_q [(size_t)BB * SS * CC];   // [b][s][c]
__device__ __nv_bfloat16 g_k [(size_t)BB * SS * CC];   // [b][s][c]
__device__ __nv_bfloat16 g_v [(size_t)BB * CC * SS];   // [b][c][s]
__device__ __nv_bfloat16 g_p [(size_t)BB * SS * SS];   // [b][sq][sk] (exp, unnormalized)
__device__ __nv_bfloat16 g_o [(size_t)BB * SS * CC];   // [b][s][c]
__device__ __nv_bfloat16 g_w [4][(size_t)CC * CC];     // bf16 weights (gamma folded q/k/v)
__device__ float         g_psum[(size_t)BB * SS * 128];
__device__ float         g_rsum[(size_t)BB * SS];

// ---------------------------------------------------------------------------
// PTX helpers
// ---------------------------------------------------------------------------
__device__ __forceinline__ uint32_t smaddr(const void* p) {
    return (uint32_t)__cvta_generic_to_shared(p);
}
__device__ __forceinline__ void cp16(uint32_t d, const void* s) {
    asm volatile("cp.async.cg.shared.global [%0], [%1], 16;\n" :: "r"(d), "l"(s));
}
__device__ __forceinline__ void cp_commit() { asm volatile("cp.async.commit_group;\n"); }
template<int N> __device__ __forceinline__ void cp_wait() {
    asm volatile("cp.async.wait_group %0;\n" :: "n"(N));
}
__device__ __forceinline__ void ldsm4(uint32_t* r, uint32_t a) {
    asm volatile("ldmatrix.sync.aligned.m8n8.x4.shared.b16 {%0,%1,%2,%3}, [%4];"
                 : "=r"(r[0]), "=r"(r[1]), "=r"(r[2]), "=r"(r[3]) : "r"(a));
}
__device__ __forceinline__ void mma16816(float* c, const uint32_t* a, const uint32_t* b) {
    asm volatile("mma.sync.aligned.m16n8k16.row.col.f32.bf16.bf16.f32 "
                 "{%0,%1,%2,%3},{%4,%5,%6,%7},{%8,%9},{%0,%1,%2,%3};"
                 : "+f"(c[0]), "+f"(c[1]), "+f"(c[2]), "+f"(c[3])
                 : "r"(a[0]), "r"(a[1]), "r"(a[2]), "r"(a[3]), "r"(b[0]), "r"(b[1]));
}

// ---------------------------------------------------------------------------
// stagers (pre-offset row pointers)
// ---------------------------------------------------------------------------
// 128x64 tile, 128 threads, 8 chunks each
__device__ __forceinline__ void stageMK(uint32_t dst, const __nv_bfloat16* g,
                                        int ld, int k0, int tid) {
#pragma unroll
    for (int j = 0; j < 8; j++) {
        int c = j * 128 + tid;
        int row = c >> 3, off = (c & 7) << 3;
        cp16(dst + (uint32_t)(row * MKP + off) * 2, g + (size_t)row * ld + k0 + off);
    }
}
// 128x64 tile, 256 threads, 4 chunks each
__device__ __forceinline__ void stageA256(uint32_t dst, const __nv_bfloat16* g,
                                          int ld, int k0, int tid) {
#pragma unroll
    for (int j = 0; j < 4; j++) {
        int c = j * 256 + tid;
        int row = c >> 3, off = (c & 7) << 3;
        cp16(dst + (uint32_t)(row * MKP + off) * 2, g + (size_t)row * ld + k0 + off);
    }
}
// 256x64 tile, 256 threads, 8 chunks each
__device__ __forceinline__ void stageB256(uint32_t dst, const __nv_bfloat16* g,
                                          int ld, int k0, int tid) {
#pragma unroll
    for (int j = 0; j < 8; j++) {
        int c = j * 256 + tid;
        int row = c >> 3, off = (c & 7) << 3;
        cp16(dst + (uint32_t)(row * MKP + off) * 2, g + (size_t)row * ld + k0 + off);
    }
}

// ---------------------------------------------------------------------------
// fragment loaders (warp tile 64x64)
// ---------------------------------------------------------------------------
__device__ __forceinline__ void fragA_MK(uint32_t a[4][4], uint32_t base,
                                         int wm, int lane, int ks) {
    int g = lane >> 3;
#pragma unroll
    for (int mt = 0; mt < 4; mt++) {
        int row = wm + mt * 16 + ((g & 1) << 3) + (lane & 7);
        int col = ks * 16 + ((g >> 1) << 3);
        ldsm4(a[mt], base + (uint32_t)(row * MKP + col) * 2);
    }
}
__device__ __forceinline__ void fragB_MK(uint32_t b[8][4], uint32_t base, int wn, int lane) {
    int g = lane >> 3;
#pragma unroll
    for (int nt = 0; nt < 8; nt++) {
        int row = wn + nt * 8 + (lane & 7);
        int col = g << 3;
        ldsm4(b[nt], base + (uint32_t)(row * MKP + col) * 2);
    }
}

#define ACC_INIT                                                      \
    float acc[4][8][4];                                               \
    _Pragma("unroll") for (int mt = 0; mt < 4; mt++)                  \
    _Pragma("unroll") for (int nt = 0; nt < 8; nt++)                  \
    _Pragma("unroll") for (int i = 0; i < 4; i++) acc[mt][nt][i] = 0.f;

#define SLAB_BF(baseA, baseB)                                         \
    {                                                                 \
        uint32_t bfr[8][4];                                           \
        fragB_MK(bfr, (baseB), wn, lane);                             \
        _Pragma("unroll")                                             \
        for (int ks = 0; ks < 2; ks++) {                              \
            uint32_t afr[4][4];                                       \
            fragA_MK(afr, (baseA), wm, lane, ks);                     \
            _Pragma("unroll") for (int mt = 0; mt < 4; mt++)          \
            _Pragma("unroll") for (int nt = 0; nt < 8; nt++)          \
                mma16816(acc[mt][nt], afr[mt], &bfr[nt][ks * 2]);     \
        }                                                             \
    }
#define SLAB64_BF(baseA, baseB)                                       \
    SLAB_BF((baseA), (baseB));                                        \
    SLAB_BF((baseA) + HALF_MK, (baseB) + HALF_MK);

#define ROT3(s0, s1, s2) { uint32_t _t = s0; s0 = s1; s1 = s2; s2 = _t; }

// 128-thread mainloop (128x128 tile)
#define GEMM_VARS128                                                  \
    extern __shared__ __align__(16) char dynsm[];                     \
    uint32_t sbase = smaddr(dynsm);                                   \
    int tid = threadIdx.x, lane = tid & 31, wid = tid >> 5;           \
    int wm = (wid >> 1) * 64, wn = (wid & 1) * 64;                    \
    int qr = lane >> 2, qc = lane & 3;                                \
    ACC_INIT

#define MAINLOOP3(gA, ldA, gB, ldB, nIt)                              \
    uint32_t a0 = sbase, a1 = a0 + SZ_MK, a2 = a1 + SZ_MK;            \
    uint32_t b0 = sbase + 3 * SZ_MK, b1 = b0 + SZ_MK, b2 = b1 + SZ_MK;\
    stageMK(a0, gA, ldA, 0, tid);                                     \
    stageMK(b0, gB, ldB, 0, tid); cp_commit();                        \
    stageMK(a1, gA, ldA, KSLAB, tid);                                 \
    stageMK(b1, gB, ldB, KSLAB, tid); cp_commit();                    \
    for (int i = 0; i < (nIt); i++) {                                 \
        cp_wait<1>();                                                 \
        __syncthreads();                                              \
        SLAB64_BF(a0, b0);                                            \
        if (i + 2 < (nIt)) {                                          \
            stageMK(a2, gA, ldA, (i + 2) * KSLAB, tid);               \
            stageMK(b2, gB, ldB, (i + 2) * KSLAB, tid);               \
            cp_commit();                                              \
        }                                                             \
        ROT3(a0, a1, a2); ROT3(b0, b1, b2);                           \
    }

// 256-thread mainloop (128x256 tile; A 128 rows, B 256 rows)
#define GEMM_VARS256                                                  \
    extern __shared__ __align__(16) char dynsm[];                     \
    uint32_t sbase = smaddr(dynsm);                                   \
    int tid = threadIdx.x, lane = tid & 31, wid = tid >> 5;           \
    int wm = (wid >> 2) * 64, wn = (wid & 3) * 64;                    \
    int qr = lane >> 2, qc = lane & 3;                                \
    ACC_INIT

#define MAINLOOP3W(gA, ldA, gB, ldB, nIt)                             \
    uint32_t a0 = sbase, a1 = a0 + SZ_MK, a2 = a1 + SZ_MK;            \
    uint32_t b0 = sbase + 3 * SZ_MK, b1 = b0 + SZ_MKB, b2 = b1 + SZ_MKB;\
    stageA256(a0, gA, ldA, 0, tid);                                   \
    stageB256(b0, gB, ldB, 0, tid); cp_commit();                      \
    stageA256(a1, gA, ldA, KSLAB, tid);                               \
    stageB256(b1, gB, ldB, KSLAB, tid); cp_commit();                  \
    for (int i = 0; i < (nIt); i++) {                                 \
        cp_wait<1>();                                                 \
        __syncthreads();                                              \
        SLAB64_BF(a0, b0);                                            \
        if (i + 2 < (nIt)) {                                          \
            stageA256(a2, gA, ldA, (i + 2) * KSLAB, tid);             \
            stageB256(b2, gB, ldB, (i + 2) * KSLAB, tid);             \
            cp_commit();                                              \
        }                                                             \
        ROT3(a0, a1, a2); ROT3(b0, b1, b2);                           \
    }

// ---------------------------------------------------------------------------
// prep: fp32 weights -> bf16; gamma folded into q/k/v weights
// ---------------------------------------------------------------------------
__global__ void prep_w_kernel(const float* __restrict__ wq, const float* __restrict__ wk,
                              const float* __restrict__ wv, const float* __restrict__ wo,
                              const float* __restrict__ gamma) {
    int which = blockIdx.y;
    const float* w = which == 0 ? wq : which == 1 ? wk : which == 2 ? wv : wo;
    int i = blockIdx.x * 256 + threadIdx.x;
    float gm = (which < 3) ? gamma[i & (CC - 1)] : 1.f;
    g_w[which][i] = __float2bfloat16_rn(w[i] * gm);
}

// ---------------------------------------------------------------------------
// fused norm + transpose (per batch)
// ---------------------------------------------------------------------------
__global__ void __launch_bounds__(256) normtrans_kernel(const float* __restrict__ x, int b) {
    extern __shared__ __align__(16) float sm[];   // 512 x 33 floats
    __shared__ float red[8][32];
    int s0 = blockIdx.x * 32;
    int tid = threadIdx.x;

    const float* xb = x + (size_t)b * CC * SS + s0;
#pragma unroll
    for (int j = 0; j < 64; j++) {
        int idx = j * 256 + tid;
        int c = idx >> 5, s = idx & 31;
        sm[c * 33 + s] = xb[(size_t)c * SS + s];
    }
    __syncthreads();

    int g = tid >> 5, s = tid & 31;
    float ss = 0.f;
#pragma unroll 8
    for (int c = g * 64; c < g * 64 + 64; c++) {
        float v = sm[c * 33 + s];
        ss += v * v;
    }
    red[g][s] = ss;
    __syncthreads();
    if (tid < 32) {
        float tot = 0.f;
#pragma unroll
        for (int j = 0; j < 8; j++) tot += red[j][tid];
        g_scale[b * SS + s0 + tid] = SQRT_C / fmaxf(sqrtf(tot), 1e-12f);
    }

    __nv_bfloat16* H = g_hn + ((size_t)b * SS + s0) * CC;
#pragma unroll 4
    for (int row = 0; row < 32; row++) {
        float v0 = sm[(2 * tid)     * 33 + row];
        float v1 = sm[(2 * tid + 1) * 33 + row];
        *(__nv_bfloat162*)&H[(size_t)row * CC + 2 * tid] = __floats2bfloat162_rn(v0, v1);
    }
}

// ---------------------------------------------------------------------------
// merged q/k/v projection (per batch, 128 threads). z = which.
// ---------------------------------------------------------------------------
__global__ void __launch_bounds__(128) proj_kernel(
    const float* __restrict__ bq, const float* __restrict__ bk,
    const float* __restrict__ bv, int b) {

    int which = blockIdx.z;
    int bx = blockIdx.x * 128;   // s block
    int by = blockIdx.y * 128;   // co block
    const __nv_bfloat16* HN = g_hn + (size_t)b * SS * CC;
    const __nv_bfloat16* W  = g_w[which];

    const __nv_bfloat16* gA = (which < 2) ? HN + (size_t)bx * CC : W + (size_t)by * CC;
    const __nv_bfloat16* gB = (which < 2) ? W + (size_t)by * CC : HN + (size_t)bx * CC;

    GEMM_VARS128
    MAINLOOP3(gA, CC, gB, CC, CC / KSLAB)

    if (which < 2) {
        const float* bias = which ? bk : bq;
        __nv_bfloat16* Qout = (which ? g_k : g_q) + (size_t)b * SS * CC;
#pragma unroll
        for (int mt = 0; mt < 4; mt++) {
            int m = bx + wm + mt * 16 + qr;
            float scm0 = g_scale[b * SS + m];
            float scm1 = g_scale[b * SS + m + 8];
#pragma unroll
            for (int nt = 0; nt < 8; nt++) {
                int n = by + wn + nt * 8 + qc * 2;
                float bi0 = bias[n], bi1 = bias[n + 1];
                *(__nv_bfloat162*)&Qout[(size_t)m * CC + n] =
                    __floats2bfloat162_rn(acc[mt][nt][0] * scm0 + bi0,
                                          acc[mt][nt][1] * scm0 + bi1);
                *(__nv_bfloat162*)&Qout[(size_t)(m + 8) * CC + n] =
                    __floats2bfloat162_rn(acc[mt][nt][2] * scm1 + bi0,
                                          acc[mt][nt][3] * scm1 + bi1);
            }
        }
    } else {
        __nv_bfloat16* Vout = g_v + (size_t)b * CC * SS;
#pragma unroll
        for (int mt = 0; mt < 4; mt++) {
            int m = by + wm + mt * 16 + qr;
            float bi0 = bv[m], bi1 = bv[m + 8];
#pragma unroll
            for (int nt = 0; nt < 8; nt++) {
                int n = bx + wn + nt * 8 + qc * 2;
                float scn0 = g_scale[b * SS + n];
                float scn1 = g_scale[b * SS + n + 1];
                *(__nv_bfloat162*)&Vout[(size_t)m * SS + n] =
                    __floats2bfloat162_rn(acc[mt][nt][0] * scn0 + bi0,
                                          acc[mt][nt][1] * scn1 + bi0);
                *(__nv_bfloat162*)&Vout[(size_t)(m + 8) * SS + n] =
                    __floats2bfloat162_rn(acc[mt][nt][2] * scn0 + bi1,
                                          acc[mt][nt][3] * scn1 + bi1);
            }
        }
    }
}

// ---------------------------------------------------------------------------
// QK^T (per batch, 256 threads, 128x256 tile, compacted grid over allowed tiles)
// ---------------------------------------------------------------------------
__global__ void __launch_bounds__(256) qk_kernel(int b) {
    int bi = blockIdx.x;   // [0, 1152)
    int f = 0;
    while (bi >= 32 * (f + 1)) { bi -= 32 * (f + 1); f++; }
    int r  = bi / (4 * (f + 1));
    int nc = bi % (4 * (f + 1));
    int m0 = (f * 8 + r) * 128;   // sq
    int n0 = nc * 256;            // sk

    const __nv_bfloat16* Q = g_q + (size_t)b * SS * CC + (size_t)m0 * CC;
    const __nv_bfloat16* K = g_k + (size_t)b * SS * CC + (size_t)n0 * CC;
    GEMM_VARS256
    MAINLOOP3W(Q, CC, K, CC, CC / KSLAB)

    __nv_bfloat16* P = g_p + (size_t)b * SS * SS;
    int pidx = (n0 >> 6) + (wn >> 6);
#pragma unroll
    for (int mt = 0; mt < 4; mt++) {
        int m = m0 + wm + mt * 16 + qr;
        float r0 = 0.f, r1 = 0.f;
#pragma unroll
        for (int nt = 0; nt < 8; nt++) {
            int n = n0 + wn + nt * 8 + qc * 2;
            float e0 = __expf(acc[mt][nt][0] * INV_SQRT_C);
            float e1 = __expf(acc[mt][nt][1] * INV_SQRT_C);
            float e2 = __expf(acc[mt][nt][2] * INV_SQRT_C);
            float e3 = __expf(acc[mt][nt][3] * INV_SQRT_C);
            *(__nv_bfloat162*)&P[(size_t)m * SS + n]       = __floats2bfloat162_rn(e0, e1);
            *(__nv_bfloat162*)&P[(size_t)(m + 8) * SS + n] = __floats2bfloat162_rn(e2, e3);
            r0 += e0 + e1;
            r1 += e2 + e3;
        }
        r0 += __shfl_xor_sync(0xffffffffu, r0, 1);
        r0 += __shfl_xor_sync(0xffffffffu, r0, 2);
        r1 += __shfl_xor_sync(0xffffffffu, r1, 1);
        r1 += __shfl_xor_sync(0xffffffffu, r1, 2);
        if (qc == 0) {
            g_psum[((size_t)b * SS + m) * 128 + pidx]     = r0;
            g_psum[((size_t)b * SS + m + 8) * 128 + pidx] = r1;
        }
    }
}

// ---------------------------------------------------------------------------
// fold partial sums -> g_rsum (per batch)
// ---------------------------------------------------------------------------
__global__ void __launch_bounds__(128) psum_reduce_kernel(int b) {
    int sq = blockIdx.x * 4 + (threadIdx.x >> 5);
    int lane = threadIdx.x & 31;
    int cnt = ((sq / NHW) + 1) * 16;
    const float* p = g_psum + ((size_t)b * SS + sq) * 128;
    float s = 0.f;
#pragma unroll
    for (int j = 0; j < 4; j++) {
        int idx = j * 32 + lane;
        if (idx < cnt) s += p[idx];
    }
#pragma unroll
    for (int o = 16; o > 0; o >>= 1) s += __shfl_xor_sync(0xffffffffu, s, o);
    if (lane == 0) g_rsum[b * SS + sq] = s;
}

// ---------------------------------------------------------------------------
// PV (per batch, 256 threads, 128x256 tile)
// ---------------------------------------------------------------------------
__global__ void __launch_bounds__(256) pv_kernel(int b) {
    int m0 = blockIdx.y * 128;   // sq
    int n0 = blockIdx.x * 256;   // c
    int L  = (m0 / NHW + 1) * NHW;
    const int nIt = L / KSLAB;

    const __nv_bfloat16* P = g_p + (size_t)b * SS * SS + (size_t)m0 * SS;
    const __nv_bfloat16* V = g_v + (size_t)b * CC * SS + (size_t)n0 * SS;
    GEMM_VARS256
    MAINLOOP3W(P, SS, V, SS, nIt)

    __nv_bfloat16* O = g_o + (size_t)b * SS * CC;
#pragma unroll
    for (int mt = 0; mt < 4; mt++) {
        int m = m0 + wm + mt * 16 + qr;
        float inv0 = 1.f / g_rsum[b * SS + m];
        float inv1 = 1.f / g_rsum[b * SS + m + 8];
#pragma unroll
        for (int nt = 0; nt < 8; nt++) {
            int n = n0 + wn + nt * 8 + qc * 2;
            *(__nv_bfloat162*)&O[(size_t)m * CC + n] =
                __floats2bfloat162_rn(acc[mt][nt][0] * inv0, acc[mt][nt][1] * inv0);
            *(__nv_bfloat162*)&O[(size_t)(m + 8) * CC + n] =
                __floats2bfloat162_rn(acc[mt][nt][2] * inv1, acc[mt][nt][3] * inv1);
        }
    }
}

// ---------------------------------------------------------------------------
// O-proj + residual (per batch, fp32 out, 128 threads)
// ---------------------------------------------------------------------------
__global__ void __launch_bounds__(128) oproj_kernel(
    const float* __restrict__ bo, const float* __restrict__ x,
    float* __restrict__ out, int b) {

    int m0 = blockIdx.y * 128;   // c_out
    int n0 = blockIdx.x * 128;   // s

    const __nv_bfloat16* W = g_w[3] + (size_t)m0 * CC;
    const __nv_bfloat16* O = g_o + (size_t)b * SS * CC + (size_t)n0 * CC;
    GEMM_VARS128
    MAINLOOP3(W, CC, O, CC, CC / KSLAB)

#pragma unroll
    for (int mt = 0; mt < 4; mt++) {
        int m = m0 + wm + mt * 16 + qr;
        float bi0 = bo[m], bi1 = bo[m + 8];
#pragma unroll
        for (int nt = 0; nt < 8; nt++) {
            int n = n0 + wn + nt * 8 + qc * 2;
            const float2 x0 = *(const float2*)&x[((size_t)b * CC + m) * SS + n];
            const float2 x1 = *(const float2*)&x[((size_t)b * CC + m + 8) * SS + n];
            float2 v0 = make_float2(acc[mt][nt][0] + bi0 + x0.x, acc[mt][nt][1] + bi0 + x0.y);
            float2 v1 = make_float2(acc[mt][nt][2] + bi1 + x1.x, acc[mt][nt][3] + bi1 + x1.y);
            *(float2*)&out[((size_t)b * CC + m) * SS + n]     = v0;
            *(float2*)&out[((size_t)b * CC + m + 8) * SS + n] = v1;
        }
    }
}

// ---------------------------------------------------------------------------
extern "C" void kernel_launch(void* const* d_in, const int* in_sizes, int n_in,
                              void* d_out, int out_size) {
    const float* x     = (const float*)d_in[0];
    const float* gamma = (const float*)d_in[1];
    const float* wq    = (const float*)d_in[2];
    const float* bq    = (const float*)d_in[3];
    const float* wk    = (const float*)d_in[4];
    const float* bk    = (const float*)d_in[5];
    const float* wv    = (const float*)d_in[6];
    const float* bv    = (const float*)d_in[7];
    const float* wo    = (const float*)d_in[8];
    const float* bo    = (const float*)d_in[9];
    float* out = (float*)d_out;

    static cudaStream_t s1 = nullptr;
    static cudaEvent_t evFork, evPrep, evDone1;
    if (!s1) {
        cudaStreamCreateWithFlags(&s1, cudaStreamNonBlocking);
        cudaEventCreateWithFlags(&evFork,  cudaEventDisableTiming);
        cudaEventCreateWithFlags(&evPrep,  cudaEventDisableTiming);
        cudaEventCreateWithFlags(&evDone1, cudaEventDisableTiming);
        cudaFuncSetAttribute(normtrans_kernel, cudaFuncAttributeMaxDynamicSharedMemorySize, SMEM_NT);
        cudaFuncSetAttribute(proj_kernel,   cudaFuncAttributeMaxDynamicSharedMemorySize, SMEM_GEMM);
        cudaFuncSetAttribute(qk_kernel,     cudaFuncAttributeMaxDynamicSharedMemorySize, SMEM_WIDE);
        cudaFuncSetAttribute(pv_kernel,     cudaFuncAttributeMaxDynamicSharedMemorySize, SMEM_WIDE);
        cudaFuncSetAttribute(oproj_kernel,  cudaFuncAttributeMaxDynamicSharedMemorySize, SMEM_GEMM);
    }

    // fork s1 from stream 0
    cudaEventRecord(evFork, 0);
    cudaStreamWaitEvent(s1, evFork, 0);

    // s1: weight prep + batch-1 chain
    prep_w_kernel<<<dim3(CC * CC / 256, 4), 256, 0, s1>>>(wq, wk, wv, wo, gamma);
    cudaEventRecord(evPrep, s1);
    normtrans_kernel<<<dim3(SS / 32, 1), 256, SMEM_NT, s1>>>(x, 1);
    proj_kernel<<<dim3(SS / 128, CC / 128, 3), 128, SMEM_GEMM, s1>>>(bq, bk, bv, 1);
    qk_kernel<<<dim3(1152, 1, 1), 256, SMEM_WIDE, s1>>>(1);
    psum_reduce_kernel<<<dim3(SS / 4, 1), 128, 0, s1>>>(1);
    pv_kernel<<<dim3(CC / 256, SS / 128, 1), 256, SMEM_WIDE, s1>>>(1);
    oproj_kernel<<<dim3(SS / 128, CC / 128, 1), 128, SMEM_GEMM, s1>>>(bo, x, out, 1);
    cudaEventRecord(evDone1, s1);

    // stream 0: batch-0 chain (proj waits on weight prep)
    normtrans_kernel<<<dim3(SS / 32, 1), 256, SMEM_NT>>>(x, 0);
    cudaStreamWaitEvent(0, evPrep, 0);
    proj_kernel<<<dim3(SS / 128, CC / 128, 3), 128, SMEM_GEMM>>>(bq, bk, bv, 0);
    qk_kernel<<<dim3(1152, 1, 1), 256, SMEM_WIDE>>>(0);
    psum_reduce_kernel<<<dim3(SS / 4, 1), 128>>>(0);
    pv_kernel<<<dim3(CC / 256, SS / 128, 1), 256, SMEM_WIDE>>>(0);
    oproj_kernel<<<dim3(SS / 128, CC / 128, 1), 128, SMEM_GEMM>>>(bo, x, out, 0);

    // join s1 back into stream 0 (required for graph capture)
    cudaStreamWaitEvent(0, evDone1, 0);
}